// round 4
// baseline (speedup 1.0000x reference)
#include <cuda_runtime.h>
#include <cstdint>
#include <cstddef>

#define T_STEPS 2048
#define BATCH   64
#define DIM     256
#define UNITS   512
#define PCOLS   1536     // 2U (xz) + U (xu)
#define ROWPAD  516      // 512 + 4 pad (keeps 16B alignment, breaks bank conflicts)
#define N_CG    16       // column groups
#define N_BG    8        // batch groups
#define BLOC    8        // batches per group

// ---------------- scratch (static device allocs are the sanctioned workaround) ----
__device__ float    g_P[(size_t)T_STEPS * PCOLS * BATCH];   // [t][col][batch] fp32
__device__ float    g_h [BATCH * UNITS];
__device__ float    g_hr[BATCH * UNITS];
__device__ float    g_zt[BATCH * UNITS];
__device__ unsigned g_bar[N_BG];

static __device__ __forceinline__ float sigmoidf_(float z) {
    return 1.0f / (1.0f + __expf(-z));
}

// ---------------- init: zero h0 and barrier counters every launch -----------------
__global__ void gru_init() {
    int i = blockIdx.x * blockDim.x + threadIdx.x;
    if (i < BATCH * UNITS) g_h[i] = 0.0f;
    if (i < N_BG) g_bar[i] = 0u;
}

// ---------------- projection GEMM: P[t][c][b] = sum_d x[b][t][d] * W[d][c] --------
// grid = (12 col-tiles of 128, 2048 t), 256 threads, tile [64b x 128c], K=256
__global__ void __launch_bounds__(256, 1)
gru_proj(const float* __restrict__ x, const float* __restrict__ Wk,
         const float* __restrict__ Wu) {
    extern __shared__ float sm[];
    float* xs = sm;               // [64][260]  (pad 4)
    float* ws = sm + 64 * 260;    // [256][128]

    const int tid = threadIdx.x;
    const int t   = blockIdx.y;
    const int c0  = blockIdx.x * 128;

    const float* Wsrc;
    int ldw, cbase;
    if (c0 < 2 * UNITS) { Wsrc = Wk; ldw = 2 * UNITS; cbase = c0; }
    else                { Wsrc = Wu; ldw = UNITS;     cbase = c0 - 2 * UNITS; }

    // stage x tile [64b][256d]
    for (int i = tid; i < 64 * 64; i += 256) {
        int b = i >> 6, dq = i & 63;
        float4 v = *(const float4*)(x + ((size_t)b * T_STEPS + t) * DIM + dq * 4);
        *(float4*)(xs + b * 260 + dq * 4) = v;
    }
    // stage W tile [256d][128c]
    for (int i = tid; i < 256 * 32; i += 256) {
        int d = i >> 5, cq = i & 31;
        float4 v = *(const float4*)(Wsrc + (size_t)d * ldw + cbase + cq * 4);
        *(float4*)(ws + d * 128 + cq * 4) = v;
    }
    __syncthreads();

    const int q  = tid & 15;       // b-quad: batches q*4..q*4+3
    const int cb = (tid >> 4) * 8; // 8 consecutive cols

    float acc[4][8];
#pragma unroll
    for (int i = 0; i < 4; ++i)
#pragma unroll
        for (int j = 0; j < 8; ++j) acc[i][j] = 0.0f;

#pragma unroll 4
    for (int k = 0; k < 256; ++k) {
        float xv[4];
#pragma unroll
        for (int i = 0; i < 4; ++i) xv[i] = xs[(q * 4 + i) * 260 + k];
        float4 w0 = *(const float4*)(ws + k * 128 + cb);
        float4 w1 = *(const float4*)(ws + k * 128 + cb + 4);
        float wv[8] = { w0.x, w0.y, w0.z, w0.w, w1.x, w1.y, w1.z, w1.w };
#pragma unroll
        for (int i = 0; i < 4; ++i)
#pragma unroll
            for (int j = 0; j < 8; ++j)
                acc[i][j] = fmaf(xv[i], wv[j], acc[i][j]);
    }

    // store P[t][c0+cb+j][q*4 .. q*4+3]  (streaming: written once, read once)
    float* outp = g_P + ((size_t)t * PCOLS + c0 + cb) * BATCH + q * 4;
#pragma unroll
    for (int j = 0; j < 8; ++j) {
        float4 v = make_float4(acc[0][j], acc[1][j], acc[2][j], acc[3][j]);
        __stcs((float4*)(outp + (size_t)j * BATCH), v);
    }
}

// ---------------- batch-group barrier (16 CTAs per counter, monotone) --------------
// Release: __threadfence before the atomicAdd. Acquire: __threadfence after the
// spin observes the target, BEFORE the releasing __syncthreads — without it the
// post-barrier global reads have no formal ordering vs. other CTAs' stores.
static __device__ __forceinline__ void bg_barrier(unsigned* ctr, unsigned target) {
    __threadfence();          // order this CTA's prior global stores (release)
    __syncthreads();          // whole CTA done (and fenced)
    if (threadIdx.x == 0) {
        atomicAdd(ctr, 1u);
        volatile unsigned* vc = ctr;
        while (*vc < target) { __nanosleep(40); }   // backoff: keep L2 quiet
        __threadfence();      // acquire: order subsequent reads after observation
    }
    __syncthreads();
}

// ---------------- persistent recurrence kernel ------------------------------------
// grid = 128 CTAs: cg = blockIdx.x & 15 (column group), bg = blockIdx.x >> 4 (batch group)
__global__ void __launch_bounds__(256, 1)
gru_rec(const float* __restrict__ Wrk, const float* __restrict__ brk,
        const float* __restrict__ Wur, const float* __restrict__ bur,
        float* __restrict__ out) {
    extern __shared__ float sm[];
    float* WrkS = sm;                    // [64][516]  this cg's 64 z-cols, k-contig
    float* WurS = sm + 64 * ROWPAD;      // [32][516]  this cg's 32 u-cols
    float* HS   = sm + 96 * ROWPAD;      // [8][516]   staged h (then hr)

    const int tid = threadIdx.x;
    const int cg  = blockIdx.x & 15;
    const int bg  = blockIdx.x >> 4;

    // load weight slices (transposed: [col][k]) — resident for all 2048 steps
    for (int i = tid; i < 512 * 64; i += 256) {
        int k = i >> 6, c = i & 63;
        WrkS[c * ROWPAD + k] = Wrk[(size_t)k * (2 * UNITS) + cg * 64 + c];
    }
    for (int i = tid; i < 512 * 32; i += 256) {
        int k = i >> 5, c = i & 31;
        WurS[c * ROWPAD + k] = Wur[(size_t)k * UNITS + cg * 32 + c];
    }

    // phase-A mapping: 64 cols x 4 batch-pairs
    const int cA    = tid & 63;
    const int bh    = tid >> 6;                // 0..3 -> batches 2bh, 2bh+1 (local)
    const int jglob = cg * 64 + cA;            // z column 0..1023
    const float brkv = brk[jglob];
    const int b0    = bg * BLOC + 2 * bh;      // global batch of first lane output

    // phase-B mapping: 32 cols x 8 batches
    const int cB    = tid & 31;
    const int bB    = tid >> 5;                // 0..7 local batch
    const int uglob = cg * 32 + cB;            // u column 0..511
    const float burv = bur[uglob];
    const int bPB   = bg * BLOC + bB;

    unsigned* ctr = &g_bar[bg];
    unsigned target = 0;

    const float* pA = g_P + (size_t)jglob * BATCH + b0;            // xz stream
    const float* pB = g_P + (size_t)(2 * UNITS + uglob) * BATCH + bPB; // xu stream
    const size_t pstride = (size_t)PCOLS * BATCH;

    __syncthreads();   // weights staged

    float2 xz = __ldcs((const float2*)pA);     // prefetch step-0 xz

    for (int t = 0; t < T_STEPS; ++t) {
        // ---- stage h[bg*8 .. +8][0..512) into HS[b][k] ----
        for (int i = tid; i < BLOC * 128; i += 256) {
            int b = i >> 7, kq = i & 127;
            float4 v = __ldcg((const float4*)&g_h[(size_t)(bg * BLOC + b) * UNITS + kq * 4]);
            *(float4*)&HS[b * ROWPAD + kq * 4] = v;
        }
        __syncthreads();

        // ---- phase A: z[b, jglob] = xz + h . WrkS[:,cA] ----
        {
            const float4* wr  = (const float4*)(WrkS + cA * ROWPAD);
            const float4* h0p = (const float4*)(HS + (2 * bh) * ROWPAD);
            const float4* h1p = (const float4*)(HS + (2 * bh + 1) * ROWPAD);
            float s0a = 0.f, s0b = 0.f, s1a = 0.f, s1b = 0.f;
#pragma unroll 8
            for (int k4 = 0; k4 < 128; ++k4) {
                float4 w = wr[k4];
                float4 p = h0p[k4];
                float4 r = h1p[k4];
                s0a = fmaf(w.x, p.x, s0a); s0b = fmaf(w.y, p.y, s0b);
                s0a = fmaf(w.z, p.z, s0a); s0b = fmaf(w.w, p.w, s0b);
                s1a = fmaf(w.x, r.x, s1a); s1b = fmaf(w.y, r.y, s1b);
                s1a = fmaf(w.z, r.z, s1a); s1b = fmaf(w.w, r.w, s1b);
            }
            float z0 = s0a + s0b + xz.x + brkv;
            float z1 = s1a + s1b + xz.y + brkv;
            if (jglob < UNITS) {            // r-gate columns -> write h*r
                float r0 = sigmoidf_(z0), r1 = sigmoidf_(z1);
                float hv0 = HS[(2 * bh) * ROWPAD + jglob];
                float hv1 = HS[(2 * bh + 1) * ROWPAD + jglob];
                __stcg(&g_hr[(size_t)b0 * UNITS + jglob], hv0 * r0);
                __stcg(&g_hr[(size_t)(b0 + 1) * UNITS + jglob], hv1 * r1);
            } else {                        // update-gate columns -> write z_t
                int u = jglob - UNITS;
                __stcg(&g_zt[(size_t)b0 * UNITS + u], sigmoidf_(z0));
                __stcg(&g_zt[(size_t)(b0 + 1) * UNITS + u], sigmoidf_(z1));
            }
        }
        target += N_CG;
        bg_barrier(ctr, target);            // barrier 1: hr & zt complete

        // ---- stage hr into HS (overwrite) + independent loads ----
        for (int i = tid; i < BLOC * 128; i += 256) {
            int b = i >> 7, kq = i & 127;
            float4 v = __ldcg((const float4*)&g_hr[(size_t)(bg * BLOC + b) * UNITS + kq * 4]);
            *(float4*)&HS[b * ROWPAD + kq * 4] = v;
        }
        const float xu   = __ldcs(pB);
        const float ztv  = __ldcg(&g_zt[(size_t)bPB * UNITS + uglob]);
        const float hold = __ldcg(&g_h [(size_t)bPB * UNITS + uglob]);
        __syncthreads();

        // prefetch next step's xz (overlaps phase-B math)
        pA += pstride;
        if (t + 1 < T_STEPS) xz = __ldcs((const float2*)pA);

        // ---- phase B: ht = tanh(xu + hr . WurS[:,cB] + bur); combine ----
        {
            const float4* wu4 = (const float4*)(WurS + cB * ROWPAD);
            const float4* hb4 = (const float4*)(HS + bB * ROWPAD);
            float sa = 0.f, sb = 0.f;
#pragma unroll 8
            for (int k4 = 0; k4 < 128; ++k4) {
                float4 w = wu4[k4];
                float4 h = hb4[k4];
                sa = fmaf(w.x, h.x, sa); sb = fmaf(w.y, h.y, sb);
                sa = fmaf(w.z, h.z, sa); sb = fmaf(w.w, h.w, sb);
            }
            float ht   = tanhf(sa + sb + xu + burv);
            float hnew = (1.0f - ztv) * hold + ztv * ht;
            __stcg(&g_h[(size_t)bPB * UNITS + uglob], hnew);
            if (t == T_STEPS - 1)
                out[(size_t)bPB * UNITS + uglob] = hnew;
        }
        target += N_CG;
        bg_barrier(ctr, target);            // barrier 2: h updated

        pB += pstride;
    }
}

// ---------------- launch ----------------------------------------------------------
extern "C" void kernel_launch(void* const* d_in, const int* in_sizes, int n_in,
                              void* d_out, int out_size) {
    (void)in_sizes; (void)n_in; (void)out_size;
    const float* x   = (const float*)d_in[0];
    const float* Wk  = (const float*)d_in[1];
    const float* Wrk = (const float*)d_in[2];
    const float* brk = (const float*)d_in[3];
    const float* Wu  = (const float*)d_in[4];
    const float* Wur = (const float*)d_in[5];
    const float* bur = (const float*)d_in[6];
    float* out = (float*)d_out;

    const int smemProj = (64 * 260 + 256 * 128) * 4;   // 197632 B
    const int smemRec  = (104 * ROWPAD) * 4;           // 214656 B

    cudaFuncSetAttribute(gru_proj, cudaFuncAttributeMaxDynamicSharedMemorySize, smemProj);
    cudaFuncSetAttribute(gru_rec,  cudaFuncAttributeMaxDynamicSharedMemorySize, smemRec);

    gru_init<<<128, 256>>>();
    gru_proj<<<dim3(12, T_STEPS), 256, smemProj>>>(x, Wk, Wu);
    gru_rec<<<128, 256, smemRec>>>(Wrk, brk, Wur, bur, out);
}